// round 17
// baseline (speedup 1.0000x reference)
#include <cuda_runtime.h>
#include <cstdint>

#define TT     2190
#define NWARM  365
#define NMAIN  1825
#define NG     10000
#define NP     (NG / 2)                 // cell pairs (thread handles 2 adjacent)
#define KER    15
#define CH     25
#define BLK    64
#define DPF    12                       // prefetch depth in steps
#define RING   16                       // smem ring slots (power of 2 > DPF)
#define ROWB   (NG * 3 * 4)             // bytes per time row
#define SLOTB  (BLK * 24)               // bytes per ring slot (24B/thread)
#define SLOTF  (SLOTB / 4)              // floats per ring slot

// scratch (device globals: the sanctioned no-alloc workaround)
__device__ float g_q[NMAIN * NG];       // raw simulated discharge, 73 MB
__device__ float g_uh[KER * NG];        // per-cell unit hydrograph

// ---------------------------------------------------------------------------
struct Cell {
    float beta, inv_fc, fc, inv_lpfc, pperc, nk0uzl, tt, cfmax, mcf, cfr, cwh,
          k0, omk1, omk2;
    float sp, mw, sm, suz, slz, sw;
};

__device__ __forceinline__ void cell_init(Cell& c, const float* __restrict__ par, int g)
{
    float raw[14];
    #pragma unroll
    for (int i = 0; i < 14; ++i) raw[i] = par[g * 14 + i];
    c.beta    = 1.0f   + raw[0]  * 5.0f;
    c.fc      = 50.0f  + raw[1]  * 950.0f;
    c.k0      = 0.05f  + raw[2]  * 0.85f;
    float k1  = 0.01f  + raw[3]  * 0.49f;
    float k2  = 0.001f + raw[4]  * 0.199f;
    float lp  = 0.2f   + raw[5]  * 0.8f;
    c.pperc   =          raw[6]  * 10.0f;
    float uzl =          raw[7]  * 100.0f;
    c.tt      = -2.5f  + raw[8]  * 5.0f;
    c.cfmax   = 0.5f   + raw[9]  * 9.5f;
    c.cfr     =          raw[10] * 0.1f;
    c.cwh     =          raw[11] * 0.2f;
    c.mcf     = -c.cfmax * c.tt;
    c.nk0uzl  = -c.k0 * uzl;
    c.inv_fc  = 1.0f / c.fc;
    c.inv_lpfc= 1.0f / (lp * c.fc);
    c.omk1    = 1.0f - k1;
    c.omk2    = 1.0f - k2;
    c.sp = 0.001f; c.mw = 0.001f; c.sm = 0.001f; c.suz = 0.001f; c.slz = 0.001f;
    c.sw = __powf(c.sm * c.inv_fc, c.beta);   // soil wetness of CURRENT sm
}

// one HBV timestep — R16's chain-minimized form (proven best).
__device__ __forceinline__ float step(Cell& c, float precip, float pet, float tm)
{
    bool  P    = (tm >= c.tt);
    float rain = P ? precip : 0.0f;
    float snow = P ? 0.0f : precip;
    float d    = fmaf(c.cfmax, tm, c.mcf);       // cfmax*(tm-tt)
    float e    = P ? d : c.cfr * d;              // melt(+) / -refreeze(-)
    float pil  = pet * c.inv_lpfc;

    float sp1  = c.sp + snow;
    float f    = fminf(fmaxf(e, -c.mw), sp1);    // net melt flux
    float sp2  = sp1 - f;
    float mw2  = c.mw + f;
    float ts   = fmaxf(fmaf(-c.cwh, sp2, mw2), 0.0f);
    c.mw = mw2 - ts;
    c.sp = sp2;

    float rts  = rain + ts;
    float srts = c.sm + rts;
    float suzz = c.suz + srts;
    float a1   = fmaf(rts, c.sw, c.suz);         // suz + recharge
    float sm1  = fmaf(-rts, c.sw, srts);         // sm + rts - recharge
    float suz2 = fmaxf(a1, suzz - c.fc);         // suz + recharge + excess
    float sm2  = fminf(sm1, c.fc);
    float t2   = fminf(sm2 * pil, pet);          // pet*clip(ef,0,1)
    c.sm       = fmaxf(sm2 - t2, 1e-5f);
    c.sw       = __powf(c.sm * c.inv_fc, c.beta);    // for NEXT step

    float suz3 = fmaxf(suz2 - c.pperc, 0.0f);
    float perc = suz2 - suz3;
    float q0   = fmaxf(fmaf(c.k0, suz3, c.nk0uzl), 0.0f);
    float suz4 = suz3 - q0;
    float suzn = suz4 * c.omk1;                  // q0+q1 = suz3 - suzn
    float slz1 = c.slz + perc;
    float slzn = slz1 * c.omk2;                  // q2 = slz1 - slzn
    c.suz = suzn;
    c.slz = slzn;
    return (suz3 - suzn) + (slz1 - slzn);
}

// ---------------------------------------------------------------------------
__device__ __forceinline__ void cp8(uint32_t dst, const char* src)
{
    asm volatile("cp.async.ca.shared.global [%0], [%1], 8;"
                 :: "r"(dst), "l"(src));
}
__device__ __forceinline__ void cp_commit()
{
    asm volatile("cp.async.commit_group;");
}
__device__ __forceinline__ void cp_wait_keep10()
{
    asm volatile("cp.async.wait_group 10;");   // slots n and n+1 resident
}

// ---------------------------------------------------------------------------
// K0: gamma unit hydrograph per cell
// ---------------------------------------------------------------------------
__global__ void __launch_bounds__(256)
uh_kernel(const float* __restrict__ par)
{
    int g = blockIdx.x * blockDim.x + threadIdx.x;
    if (g >= NG) return;
    float a   = fmaf(par[g * 14 + 12], 2.9f, 0.1f);
    float th  = fmaf(par[g * 14 + 13], 6.5f, 0.5f);
    float am1 = a - 1.0f;
    float ith = 1.0f / th;

    float w[KER], s = 0.0f;
    #pragma unroll
    for (int k = 0; k < KER; ++k) {
        float tk = (float)k + 0.5f;
        w[k] = __expf(fmaf(am1, __logf(tk), -tk * ith));
        s += w[k];
    }
    float inv = 1.0f / s;
    #pragma unroll
    for (int k = 0; k < KER; ++k) g_uh[k * NG + g] = w[k] * inv;
}

// ---------------------------------------------------------------------------
// K1: sequential HBV scan — R9 skeleton, TWO ADJACENT cells per thread.
// The fixed per-step overhead (copies/commit/wait/store/loop ALU) is paid
// once per pair: 24 contiguous bytes at g0*12 (g0 even => 8-aligned) are
// copied as 3 x cp.async.8 (self-produce/self-consume, no cross-thread
// coupling), inputs staged as 3 x LDS.64, q written as one STG.64.
// ---------------------------------------------------------------------------
__global__ void __launch_bounds__(64, 1)
hbv_scan_kernel(const float* __restrict__ x, const float* __restrict__ par)
{
    __shared__ __align__(16) float ring[RING * SLOTF];   // 24 KB

    int tid = threadIdx.x;
    int i   = blockIdx.x * BLK + tid;    // pair index
    bool active = (i < NP);
    int ic  = active ? i : (NP - 1);     // clamp for param read
    int g0  = 2 * ic;                    // even cell
    int g1  = g0 + 1;                    // odd cell

    Cell cA, cB;
    cell_init(cA, par, g0);
    cell_init(cB, par, g1);

    uint32_t sb = (uint32_t)__cvta_generic_to_shared(ring) + (uint32_t)tid * 24u;
    const float2* __restrict__ myr = reinterpret_cast<const float2*>(ring + tid * 6);

    // 24B per step: [p0,e0,t0,p1,e1,t1] at byte offset g0*12 (8-aligned)
    const char* src = (const char*)x + (size_t)g0 * 12u;

    // ---- prologue: prefetch steps 0..DPF-1, then stage step 0 in registers ----
    #pragma unroll
    for (int s = 0; s < DPF; ++s) {
        uint32_t dst = sb + (uint32_t)s * SLOTB;
        if (active) { cp8(dst, src); cp8(dst + 8, src + 8); cp8(dst + 16, src + 16); }
        cp_commit();
        src += ROWB;
    }
    asm volatile("cp.async.wait_group 11;");     // slot 0 resident
    float2 v0 = myr[0], v1 = myr[1], v2 = myr[2];

    int rd = 0;           // ring slot of current step
    int wr = DPF;         // ring slot being filled

    // ---- warmup: 365 steps, copies unconditional (last target step 376) ----
    #pragma unroll 1
    for (int it = 0; it < NWARM / 5; ++it) {
        #pragma unroll
        for (int u = 0; u < 5; ++u) {
            cp_wait_keep10();                    // slots rd and rd+1 resident
            const float2* nx = myr + ((rd + 1) & (RING - 1)) * (SLOTF / 2);
            float2 n0 = nx[0], n1 = nx[1], n2 = nx[2];
            uint32_t dst = sb + (uint32_t)wr * SLOTB;
            if (active) { cp8(dst, src); cp8(dst + 8, src + 8); cp8(dst + 16, src + 16); }
            cp_commit();
            src += ROWB;
            rd = (rd + 1) & (RING - 1);
            wr = (wr + 1) & (RING - 1);
            (void)step(cA, v0.x, v0.y, v1.x);
            (void)step(cB, v1.y, v2.x, v2.y);
            v0 = n0; v1 = n1; v2 = n2;
        }
    }

    // ---- main: 1825 steps, copies guarded near the end of the series ----
    float* __restrict__ qp = g_q + g0;
    int ncpy = NWARM + DPF;                      // next copy target step
    #pragma unroll 1
    for (int it = 0; it < NMAIN / 5; ++it) {
        #pragma unroll
        for (int u = 0; u < 5; ++u) {
            cp_wait_keep10();
            const float2* nx = myr + ((rd + 1) & (RING - 1)) * (SLOTF / 2);
            float2 n0 = nx[0], n1 = nx[1], n2 = nx[2];
            uint32_t dst = sb + (uint32_t)wr * SLOTB;
            if (active && ncpy < TT) { cp8(dst, src); cp8(dst + 8, src + 8); cp8(dst + 16, src + 16); }
            cp_commit();                          // empty groups keep FIFO depth
            src += ROWB;
            ncpy++;
            rd = (rd + 1) & (RING - 1);
            wr = (wr + 1) & (RING - 1);
            float qa = step(cA, v0.x, v0.y, v1.x);
            float qb = step(cB, v1.y, v2.x, v2.y);
            v0 = n0; v1 = n1; v2 = n2;
            if (active) *reinterpret_cast<float2*>(qp) = make_float2(qa, qb);
            qp += NG;
        }
    }
    asm volatile("cp.async.wait_group 0;");      // drain before exit
}

// ---------------------------------------------------------------------------
// K2: 15-tap causal convolution — the proven R5 shift-register version.
// ---------------------------------------------------------------------------
__global__ void __launch_bounds__(256)
conv_kernel(float* __restrict__ out)
{
    int g = blockIdx.x * blockDim.x + threadIdx.x;
    if (g >= NG) return;
    int t0 = blockIdx.y * CH;

    float uh[KER];
    #pragma unroll
    for (int k = 0; k < KER; ++k) uh[k] = g_uh[k * NG + g];

    float w[KER - 1];
    #pragma unroll
    for (int j = 0; j < KER - 1; ++j) {
        int t = t0 - 1 - j;
        w[j] = (t >= 0) ? g_q[t * NG + g] : 0.0f;
    }

    #pragma unroll
    for (int s = 0; s < CH; ++s) {
        float qn = g_q[(t0 + s) * NG + g];
        float o  = uh[0] * qn;
        #pragma unroll
        for (int j = 0; j < KER - 1; ++j)
            o = fmaf(uh[j + 1], w[j], o);
        out[(t0 + s) * NG + g] = o;
        #pragma unroll
        for (int j = KER - 2; j > 0; --j) w[j] = w[j - 1];
        w[0] = qn;
    }
}

// ---------------------------------------------------------------------------
extern "C" void kernel_launch(void* const* d_in, const int* in_sizes, int n_in,
                              void* d_out, int out_size)
{
    const float* x   = (const float*)d_in[0];   // (2190, 10000, 3) f32
    const float* par = (const float*)d_in[1];   // (10000, 14) f32
    float*       out = (float*)d_out;           // (1825, 10000, 1) f32

    uh_kernel<<<(NG + 255) / 256, 256>>>(par);
    hbv_scan_kernel<<<(NP + BLK - 1) / BLK, BLK>>>(x, par);
    conv_kernel<<<dim3((NG + 255) / 256, NMAIN / CH), 256>>>(out);
}